// round 16
// baseline (speedup 1.0000x reference)
#include <cuda_runtime.h>
#include <cuda_bf16.h>
#include <mma.h>
#include <math.h>
#include <cstdint>
using namespace nvcuda;

// ---------------- constants ----------------
#define T1024 1024
#define D 1024
#define H 16
#define HD 64
#define E 8
#define F 2560
#define QKVN 3072
#define FC_N (2*F)   // 5120

typedef __nv_bfloat16 bf16;

// ---------------- scratch (device globals) ----------------
__device__ float g_qkv[T1024 * QKVN];
__device__ float g_tmp[T1024 * D];
__device__ float g_xres[T1024 * D];
__device__ float g_h12[(long)E * T1024 * FC_N];
__device__ float g_y[(long)E * T1024 * D];
__device__ int   g_cnt[E];
__device__ float g_sums[E];
__device__ int   g_tok[E * T1024];
__device__ float g_gwf[T1024];
__device__ float g_cs[T1024 * 32];
__device__ float g_sn[T1024 * 32];

__device__ bf16 b_h1[T1024 * D];
__device__ bf16 b_qkv[T1024 * QKVN];
__device__ bf16 b_attn[T1024 * D];
__device__ bf16 b_xg[E * T1024 * D];
__device__ bf16 b_act[(long)E * T1024 * F];
__device__ bf16 b_qkvw[D * QKVN];
__device__ bf16 b_aow[D * D];
__device__ bf16 b_fcw[(long)E * D * FC_N];
__device__ bf16 b_eow[(long)E * F * D];

// ---------------- cp.async helpers ----------------
__device__ __forceinline__ void cp16(unsigned int s, const void* g) {
    asm volatile("cp.async.cg.shared.global [%0], [%1], 16;\n" :: "r"(s), "l"(g));
}
__device__ __forceinline__ void cp_commit() {
    asm volatile("cp.async.commit_group;\n");
}
template<int N> __device__ __forceinline__ void cp_wait() {
    asm volatile("cp.async.wait_group %0;\n" :: "n"(N));
}

// ---------------- small kernels ----------------
// fused: zero counters + rope tables
__global__ void init_k() {
    int t = blockIdx.x, j = threadIdx.x;   // 32 threads
    if (t == 0 && j < E) { g_cnt[j] = 0; g_sums[j] = 0.f; }
    float inv = powf(10000.f, -(2.f * (float)j) / 64.f);
    float fr = (float)t * inv;
    g_cs[t * 32 + j] = cosf(fr);
    g_sn[t * 32 + j] = sinf(fr);
}

// fp32 -> bf16 convert, 8 elems/thread
__global__ void f2b_k(const float* __restrict__ src, bf16* __restrict__ dst, long n) {
    long i = ((long)blockIdx.x * 256 + threadIdx.x) * 8;
    if (i >= n) return;
    float4 a = *(const float4*)&src[i];
    float4 b = *(const float4*)&src[i + 4];
    __nv_bfloat162 r[4];
    r[0] = __floats2bfloat162_rn(a.x, a.y);
    r[1] = __floats2bfloat162_rn(a.z, a.w);
    r[2] = __floats2bfloat162_rn(b.x, b.y);
    r[3] = __floats2bfloat162_rn(b.z, b.w);
    *(uint4*)&dst[i] = *(uint4*)r;
}

__global__ void layernorm_k(const float* __restrict__ x, const float* __restrict__ w,
                            const float* __restrict__ b, bf16* __restrict__ y) {
    int t = blockIdx.x, tid = threadIdx.x;
    const float* xr = x + (long)t * D;
    float v[4], s = 0.f, ss = 0.f;
#pragma unroll
    for (int i = 0; i < 4; i++) {
        float a = xr[tid + i * 256];
        v[i] = a; s += a; ss += a * a;
    }
    __shared__ float r1[256], r2[256];
    r1[tid] = s; r2[tid] = ss; __syncthreads();
    for (int st = 128; st > 0; st >>= 1) {
        if (tid < st) { r1[tid] += r1[tid + st]; r2[tid] += r2[tid + st]; }
        __syncthreads();
    }
    float mean = r1[0] * (1.f / D);
    float var  = r2[0] * (1.f / D) - mean * mean;
    float inv  = rsqrtf(var + 1e-5f);
#pragma unroll
    for (int i = 0; i < 4; i++) {
        int d = tid + i * 256;
        y[(long)t * D + d] = __float2bfloat16((v[i] - mean) * inv * w[d] + b[d]);
    }
}

// fused: xres = x+tmp+bias ; h2 = LN(xres) ; gate softmax/argmax + routing + bf16 gather
__global__ void resgate_k(const float* __restrict__ x, const float* __restrict__ tmp,
                          const float* __restrict__ bias,
                          const float* __restrict__ w, const float* __restrict__ b,
                          const float* __restrict__ gw_mat, const float* __restrict__ gb,
                          float* __restrict__ xres) {
    int t = blockIdx.x, tid = threadIdx.x;
    int wrp = tid >> 5, lane = tid & 31;
    float v[4], s = 0.f, ss = 0.f;
#pragma unroll
    for (int i = 0; i < 4; i++) {
        int d = tid + i * 256;
        float a = x[(long)t * D + d] + tmp[(long)t * D + d] + bias[d];
        v[i] = a; s += a; ss += a * a;
        xres[(long)t * D + d] = a;
    }
    __shared__ float r1[256], r2[256];
    r1[tid] = s; r2[tid] = ss; __syncthreads();
    for (int st = 128; st > 0; st >>= 1) {
        if (tid < st) { r1[tid] += r1[tid + st]; r2[tid] += r2[tid + st]; }
        __syncthreads();
    }
    float mean = r1[0] * (1.f / D);
    float var  = r2[0] * (1.f / D) - mean * mean;
    float inv  = rsqrtf(var + 1e-5f);
    float h2v[4];
    float p[E];
#pragma unroll
    for (int e = 0; e < E; e++) p[e] = 0.f;
#pragma unroll
    for (int i = 0; i < 4; i++) {
        int d = tid + i * 256;
        float hv = (v[i] - mean) * inv * w[d] + b[d];
        h2v[i] = hv;
#pragma unroll
        for (int e = 0; e < E; e++) p[e] += hv * gw_mat[d * E + e];
    }
    __shared__ float wsum[8][E];
#pragma unroll
    for (int e = 0; e < E; e++) {
        float pv = p[e];
#pragma unroll
        for (int o = 16; o > 0; o >>= 1)
            pv += __shfl_xor_sync(0xffffffffu, pv, o);
        if (lane == 0) wsum[wrp][e] = pv;
    }
    __syncthreads();
    __shared__ int sh_slot, sh_e;
    if (tid == 0) {
        float logits[E];
        for (int e = 0; e < E; e++) {
            float acc = 0.f;
            for (int q = 0; q < 8; q++) acc += wsum[q][e];
            logits[e] = acc + gb[e];
        }
        float mx = -3.4e38f;
        for (int e = 0; e < E; e++) mx = fmaxf(mx, logits[e]);
        float Z = 0.f, pr[E];
        for (int e = 0; e < E; e++) { pr[e] = expf(logits[e] - mx); Z += pr[e]; }
        float best = -1.f; int bi = 0;
        for (int e = 0; e < E; e++) {
            float pv = pr[e] / Z;
            if (pv > best) { best = pv; bi = e; }
        }
        int slot = atomicAdd(&g_cnt[bi], 1);
        atomicAdd(&g_sums[bi], best);
        g_tok[bi * T1024 + slot] = t;
        g_gwf[t] = best;
        sh_slot = slot; sh_e = bi;
    }
    __syncthreads();
    bf16* dst = b_xg + ((long)sh_e * T1024 + sh_slot) * D;
#pragma unroll
    for (int i = 0; i < 4; i++)
        dst[tid + i * 256] = __float2bfloat16(h2v[i]);
}

// fused qkv bias + rope (table); writes bf16 qkv
__global__ void qkvpost_k(const float* __restrict__ b) {
    int t = blockIdx.x;
    const float* row = g_qkv + (long)t * QKVN;
    bf16* orow = b_qkv + (long)t * QKVN;
    for (int c = threadIdx.x; c < QKVN; c += blockDim.x) {
        float val;
        if (c < 2 * D) {
            int part = c / D;          // 0=q, 1=k
            int within = c - part * D;
            int d = within & 63;
            int j = d & 31;
            float cs = g_cs[t * 32 + j], sn = g_sn[t * 32 + j];
            int h = within >> 6;
            int base = part * D + h * HD;
            float x1 = row[base + j]      + b[base + j];
            float x2 = row[base + j + 32] + b[base + j + 32];
            val = (d < 32) ? (x1 * cs - x2 * sn) : (x1 * sn + x2 * cs);
        } else {
            val = row[c] + b[c];
        }
        orow[c] = __float2bfloat16(val);
    }
}

// ---------------- fused flash attention (double-buffered K/V) ----------------
#define FA_QP 72
#define FA_SP 132
#define FA_PP 136
#define FA_OP 68
#define OFF_Q 0
#define KV_STG (2 * 128 * FA_QP * 2)
#define OFF_KV0 (128 * FA_QP * 2)
#define OFF_S (OFF_KV0 + 2 * KV_STG)
#define OFF_P (OFF_S + 8 * 16 * FA_SP * 4)
#define OFF_O (OFF_P + 8 * 16 * FA_PP * 2)
#define OFF_M (OFF_O + 8 * 16 * FA_OP * 4)
#define OFF_L (OFF_M + 128 * 4)
#define OFF_G (OFF_L + 128 * 4)
#define FA_SMEM (OFF_G + 132 * 4)

__global__ void __launch_bounds__(256) fa_k(const int* __restrict__ ids) {
    extern __shared__ char sm[];
    bf16*  Qs = (bf16*)(sm + OFF_Q);
    float* Sb = (float*)(sm + OFF_S);
    bf16*  Pb = (bf16*)(sm + OFF_P);
    float* Ob = (float*)(sm + OFF_O);
    float* Mr = (float*)(sm + OFF_M);
    float* Lr = (float*)(sm + OFF_L);
    int*   Gf = (int*)(sm + OFF_G);
    unsigned sbase = (unsigned)__cvta_generic_to_shared(sm);

    int qt = blockIdx.x, h = blockIdx.y;
    int qbase = qt * 128;
    int tid = threadIdx.x, w = tid >> 5, lane = tid & 31;

    for (int i = tid; i < 128 * 8; i += 256) {
        int r = i >> 3, c8 = (i & 7) * 8;
        cp16(sbase + OFF_Q + (r * FA_QP + c8) * 2,
             &b_qkv[(long)(qbase + r) * QKVN + h * HD + c8]);
    }
    cp_commit();

    auto issueKV = [&](int stage, int kt) {
        unsigned kb = sbase + OFF_KV0 + stage * KV_STG;
        unsigned vb = kb + 128 * FA_QP * 2;
        for (int i = tid; i < 128 * 8; i += 256) {
            int r = i >> 3, c8 = (i & 7) * 8;
            long goff = (long)(kt * 128 + r) * QKVN + h * HD + c8;
            cp16(kb + (r * FA_QP + c8) * 2, &b_qkv[goff + D]);
            cp16(vb + (r * FA_QP + c8) * 2, &b_qkv[goff + 2 * D]);
        }
    };

    issueKV(0, 0);
    cp_commit();

    if (tid < 128) {
        int id = ids[qbase + tid];
        Gf[tid] = (id >= 2 && id < 8) ? 1 : 0;
        Mr[tid] = -3.0e38f;
        Lr[tid] = 0.f;
    }
    for (int i = tid; i < 8 * 16 * FA_OP; i += 256) Ob[i] = 0.f;
    cp_wait<1>();
    __syncthreads();
    if (tid == 0) {
        int any = 0;
        for (int i = 0; i < 128; i++) any |= Gf[i];
        Gf[128] = any ? 8 : (qt + 1);
    }
    __syncthreads();
    int ntiles = Gf[128];

    wmma::fragment<wmma::matrix_a, 16, 16, 16, bf16, wmma::row_major> qa[4];
#pragma unroll
    for (int k16 = 0; k16 < 4; k16++)
        wmma::load_matrix_sync(qa[k16], &Qs[(w * 16) * FA_QP + k16 * 16], FA_QP);

    float* Sw = Sb + w * 16 * FA_SP;
    bf16*  Pw = Pb + w * 16 * FA_PP;
    float* Ow = Ob + w * 16 * FA_OP;

    for (int kt = 0; kt < ntiles; kt++) {
        if (kt + 1 < ntiles) issueKV((kt + 1) & 1, kt + 1);
        cp_commit();
        cp_wait<1>();
        __syncthreads();

        bf16* Ks = (bf16*)(sm + OFF_KV0 + (kt & 1) * KV_STG);
        bf16* Vs = Ks + 128 * FA_QP;

        wmma::fragment<wmma::accumulator, 16, 16, 16, float> sacc[8];
#pragma unroll
        for (int j = 0; j < 8; j++) wmma::fill_fragment(sacc[j], 0.f);
#pragma unroll
        for (int k16 = 0; k16 < 4; k16++) {
#pragma unroll
            for (int j = 0; j < 8; j++) {
                wmma::fragment<wmma::matrix_b, 16, 16, 16, bf16, wmma::col_major> kb;
                wmma::load_matrix_sync(kb, &Ks[(j * 16) * FA_QP + k16 * 16], FA_QP);
                wmma::mma_sync(sacc[j], qa[k16], kb, sacc[j]);
            }
        }
#pragma unroll
        for (int j = 0; j < 8; j++)
            wmma::store_matrix_sync(&Sw[j * 16], sacc[j], FA_SP, wmma::mem_row_major);
        __syncwarp();

#pragma unroll 1
        for (int r = 0; r < 16; r++) {
            int rg = w * 16 + r;
            int q = qbase + rg;
            bool gl = Gf[rg] != 0;
            float v[4];
#pragma unroll
            for (int u = 0; u < 4; u++) {
                int c = lane + u * 32;
                int k = kt * 128 + c;
                float s = Sw[r * FA_SP + c];
                v[u] = (gl || k <= q) ? s * 0.125f : -3.4e38f;
            }
            float mx = fmaxf(fmaxf(v[0], v[1]), fmaxf(v[2], v[3]));
#pragma unroll
            for (int o = 16; o > 0; o >>= 1)
                mx = fmaxf(mx, __shfl_xor_sync(0xffffffffu, mx, o));
            float mo = Mr[rg];
            float mn = fmaxf(mo, mx);
            float al = __expf(mo - mn);
            float sum = 0.f;
#pragma unroll
            for (int u = 0; u < 4; u++) {
                float p = __expf(v[u] - mn);
                sum += p;
                Pw[r * FA_PP + lane + u * 32] = __float2bfloat16(p);
            }
#pragma unroll
            for (int o = 16; o > 0; o >>= 1)
                sum += __shfl_xor_sync(0xffffffffu, sum, o);
            Ow[r * FA_OP + lane]      *= al;
            Ow[r * FA_OP + lane + 32] *= al;
            if (lane == 0) {
                Mr[rg] = mn;
                Lr[rg] = Lr[rg] * al + sum;
            }
        }
        __syncwarp();

        wmma::fragment<wmma::accumulator, 16, 16, 16, float> oacc[4];
#pragma unroll
        for (int j = 0; j < 4; j++)
            wmma::load_matrix_sync(oacc[j], &Ow[j * 16], FA_OP, wmma::mem_row_major);
#pragma unroll
        for (int k16 = 0; k16 < 8; k16++) {
            wmma::fragment<wmma::matrix_a, 16, 16, 16, bf16, wmma::row_major> pa;
            wmma::load_matrix_sync(pa, &Pw[k16 * 16], FA_PP);
#pragma unroll
            for (int j = 0; j < 4; j++) {
                wmma::fragment<wmma::matrix_b, 16, 16, 16, bf16, wmma::row_major> vb;
                wmma::load_matrix_sync(vb, &Vs[(k16 * 16) * FA_QP + j * 16], FA_QP);
                wmma::mma_sync(oacc[j], pa, vb, oacc[j]);
            }
        }
#pragma unroll
        for (int j = 0; j < 4; j++)
            wmma::store_matrix_sync(&Ow[j * 16], oacc[j], FA_OP, wmma::mem_row_major);
        __syncthreads();
    }

#pragma unroll 1
    for (int r = 0; r < 16; r++) {
        int rg = w * 16 + r;
        float inv = 1.f / Lr[rg];
        int t = qbase + rg;
        b_attn[(long)t * D + h * HD + lane]      = __float2bfloat16(Ow[r * FA_OP + lane] * inv);
        b_attn[(long)t * D + h * HD + lane + 32] = __float2bfloat16(Ow[r * FA_OP + lane + 32] * inv);
    }
}

// ---------------- all-bf16 cp.async 3-stage pipelined tensor GEMM ----------------
template<int BM, int BN, int BK, int WM, int WN>
__global__ void __launch_bounds__((BM / WM) * (BN / WN) * 32, 2)
gemm_async(const bf16* __restrict__ A, int lda, long sA,
           const bf16* __restrict__ B, int ldb, long sB,
           float* __restrict__ C, int ldc, long sC,
           int K, const int* __restrict__ cntPtr) {
    int z = blockIdx.z;
    int m0 = blockIdx.y * BM;
    if (cntPtr && m0 >= cntPtr[z]) return;
    int n0 = blockIdx.x * BN;
    A += (long)z * sA; B += (long)z * sB; C += (long)z * sC;

    constexpr int S = 3;
    constexpr int AP = BK + 8;
    constexpr int BP = BN + 8;
    __shared__ __align__(16) bf16 As[S][BM][AP];
    __shared__ __align__(16) bf16 Bs[S][BK][BP];

    constexpr int WARPS_M = BM / WM;
    constexpr int WARPS_N = BN / WN;
    constexpr int NT = WARPS_M * WARPS_N * 32;
    constexpr int MI = WM / 16, NI = WN / 16;
    constexpr int ACH = BM * BK / 8;
    constexpr int BCH = BK * BN / 8;

    int tid = threadIdx.x;
    int w = tid >> 5;
    int wm = w % WARPS_M, wn = w / WARPS_M;
    int mw0 = wm * WM, nw0 = wn * WN;

    int nIter = K / BK;

    unsigned int sA0 = (unsigned int)__cvta_generic_to_shared(&As[0][0][0]);
    unsigned int sB0 = (unsigned int)__cvta_generic_to_shared(&Bs[0][0][0]);
    constexpr unsigned int A_STG = BM * AP * 2;
    constexpr unsigned int B_STG = BK * BP * 2;

    auto issue = [&](int stage, int k0) {
#pragma unroll
        for (int c = tid; c < ACH; c += NT) {
            int row = c / (BK / 8);
            int col = (c % (BK / 8)) * 8;
            cp16(sA0 + stage * A_STG + (row * AP + col) * 2,
                 &A[(long)(m0 + row) * lda + k0 + col]);
        }
#pragma unroll
        for (int c = tid; c < BCH; c += NT) {
            int kk = c / (BN / 8);
            int col = (c % (BN / 8)) * 8;
            cp16(sB0 + stage * B_STG + (kk * BP + col) * 2,
                 &B[(long)(k0 + kk) * ldb + n0 + col]);
        }
    };

#pragma unroll
    for (int s = 0; s < S - 1; s++) {
        if (s < nIter) issue(s, s * BK);
        cp_commit();
    }

    wmma::fragment<wmma::accumulator, 16, 16, 16, float> acc[MI][NI];
#pragma unroll
    for (int i = 0; i < MI; i++)
#pragma unroll
        for (int j = 0; j < NI; j++) wmma::fill_fragment(acc[i][j], 0.f);

    for (int it = 0; it < nIter; it++) {
        cp_wait<S - 2>();
        __syncthreads();
        int st = it % S;
#pragma unroll
        for (int k16 = 0; k16 < BK; k16 += 16) {
            wmma::fragment<wmma::matrix_b, 16, 16, 16, bf16, wmma::row_major> bfr[NI];
#pragma unroll
            for (int j = 0; j < NI; j++)
                wmma::load_matrix_sync(bfr[j], &Bs[st][k16][nw0 + j * 16], BP);
#pragma unroll
            for (int i = 0; i < MI; i++) {
                wmma::fragment<wmma::matrix_a, 16, 16, 16, bf16, wmma::row_major> af;
                wmma::load_matrix_sync(af, &As[st][mw0 + i * 16][k16], AP);
#pragma unroll
                for (int j = 0; j < NI; j++)
                    wmma::mma_sync(acc[i][j], af, bfr[j], acc[i][j]);
            }
        }
        int pf = it + S - 1;
        if (pf < nIter) issue(pf % S, pf * BK);
        cp_commit();
    }
#pragma unroll
    for (int i = 0; i < MI; i++)
#pragma unroll
        for (int j = 0; j < NI; j++)
            wmma::store_matrix_sync(&C[(long)(m0 + mw0 + i * 16) * ldc + n0 + nw0 + j * 16],
                                    acc[i][j], ldc, wmma::mem_row_major);
}

// GLU activation with fused fc bias (exact gelu) -> bf16; m-strided grid
__global__ void moe_act_k(const float* __restrict__ fcb) {
    int e = blockIdx.z;
    int cp = (g_cnt[e] + 127) & ~127;
    int f = blockIdx.x * 256 + threadIdx.x;
    const float* b = fcb + (long)e * FC_N;
    float b1 = b[f], b2 = b[F + f];
    for (int m = blockIdx.y; m < cp; m += gridDim.y) {
        const float* row = g_h12 + ((long)e * T1024 + m) * FC_N;
        float x1 = row[f] + b1;
        float x2 = row[F + f] + b2;
        float g = 0.5f * x2 * (1.f + erff(x2 * 0.70710678118654752f));
        b_act[((long)e * T1024 + m) * F + f] = __float2bfloat16(x1 * g);
    }
}

// scatter epilogue: out[t] = xres[t] + (y[m] + eout_b) * gw[t]; m-strided grid
__global__ void scatter_k(const float* __restrict__ eob, float* __restrict__ out) {
    int e = blockIdx.x;
    int cnt = g_cnt[e];
    const float* bias = eob + (long)e * D;
    for (int m = blockIdx.y; m < cnt; m += gridDim.y) {
        int t = g_tok[e * T1024 + m];
        float g = g_gwf[t];
        const float* y = g_y + ((long)e * T1024 + m) * D;
        for (int d = threadIdx.x; d < D; d += 256)
            out[(long)t * D + d] = g_xres[(long)t * D + d] + (y[d] + bias[d]) * g;
    }
}

__global__ void moe_loss_k(float* __restrict__ out_loss) {
    if (threadIdx.x == 0) {
        float l = 0.f;
        for (int e = 0; e < E; e++) {
            float u = g_sums[e] / ((float)g_cnt[e] + 1e-8f);
            float d = u - 1.f / (float)E;
            l += d * d;
        }
        out_loss[0] = l;
    }
}

// ---------------- host ----------------
static void* sym_addr(const void* sym) {
    void* p = nullptr;
    cudaGetSymbolAddress(&p, sym);
    return p;
}

extern "C" void kernel_launch(void* const* d_in, const int* in_sizes, int n_in,
                              void* d_out, int out_size) {
    const float* x      = (const float*)d_in[0];
    const int*   ids    = (const int*)d_in[1];
    const float* ln1w   = (const float*)d_in[2];
    const float* ln1b   = (const float*)d_in[3];
    const float* qkvw   = (const float*)d_in[4];
    const float* qkvb   = (const float*)d_in[5];
    const float* aow    = (const float*)d_in[6];
    const float* aob    = (const float*)d_in[7];
    const float* ln2w   = (const float*)d_in[8];
    const float* ln2b   = (const float*)d_in[9];
    const float* gatew  = (const float*)d_in[10];
    const float* gateb  = (const float*)d_in[11];
    const float* fcw    = (const float*)d_in[12];
    const float* fcb    = (const float*)d_in[13];
    const float* eow    = (const float*)d_in[14];
    const float* eob    = (const float*)d_in[15];
    float* out = (float*)d_out;

    float* p_qkv  = (float*)sym_addr(g_qkv);
    float* p_tmp  = (float*)sym_addr(g_tmp);
    float* p_xres = (float*)sym_addr(g_xres);
    float* p_h12  = (float*)sym_addr(g_h12);
    float* p_y    = (float*)sym_addr(g_y);
    int*   p_cnt  = (int*)sym_addr(g_cnt);
    bf16* pb_h1   = (bf16*)sym_addr(b_h1);
    bf16* pb_qkv  = (bf16*)sym_addr(b_qkv);
    bf16* pb_attn = (bf16*)sym_addr(b_attn);
    bf16* pb_xg   = (bf16*)sym_addr(b_xg);
    bf16* pb_act  = (bf16*)sym_addr(b_act);
    bf16* pb_qkvw = (bf16*)sym_addr(b_qkvw);
    bf16* pb_aow  = (bf16*)sym_addr(b_aow);
    bf16* pb_fcw  = (bf16*)sym_addr(b_fcw);
    bf16* pb_eow  = (bf16*)sym_addr(b_eow);

    static cudaStream_t s2 = nullptr;
    static cudaEvent_t evFork = nullptr, evJoin = nullptr;
    if (!s2) {
        cudaStreamCreateWithFlags(&s2, cudaStreamNonBlocking);
        cudaEventCreateWithFlags(&evFork, cudaEventDisableTiming);
        cudaEventCreateWithFlags(&evJoin, cudaEventDisableTiming);
        cudaFuncSetAttribute(fa_k, cudaFuncAttributeMaxDynamicSharedMemorySize, FA_SMEM);
    }

    // fork side stream: big MoE weight converts overlap the attention chain
    cudaEventRecord(evFork, 0);
    cudaStreamWaitEvent(s2, evFork, 0);
    f2b_k<<<(int)(((long)E * D * FC_N) / (8 * 256)), 256, 0, s2>>>(fcw, pb_fcw, (long)E * D * FC_N);
    f2b_k<<<(int)(((long)E * F * D) / (8 * 256)), 256, 0, s2>>>(eow, pb_eow, (long)E * F * D);
    cudaEventRecord(evJoin, s2);

    // main stream: attention chain
    init_k<<<T1024, 32>>>();
    f2b_k<<<(D * QKVN) / (8 * 256), 256>>>(qkvw, pb_qkvw, (long)D * QKVN);
    f2b_k<<<(D * D) / (8 * 256), 256>>>(aow, pb_aow, (long)D * D);

    layernorm_k<<<T1024, 256>>>(x, ln1w, ln1b, pb_h1);

    // QKV GEMM: 64x64 tiles for wave-fill (192 -> 768 CTAs)
    gemm_async<64,64,32,32,32><<<dim3(QKVN/64, T1024/64, 1), 128>>>(
        pb_h1, D, 0, pb_qkvw, QKVN, 0, p_qkv, QKVN, 0, D, nullptr);

    qkvpost_k<<<T1024, 768>>>(qkvb);

    fa_k<<<dim3(T1024/128, H), 256, FA_SMEM>>>(ids);

    // Wo GEMM: 64x64 tiles for occupancy
    gemm_async<64,64,32,32,32><<<dim3(D/64, T1024/64, 1), 128>>>(
        pb_attn, D, 0, pb_aow, D, 0, p_tmp, D, 0, D, nullptr);

    // fused residual + LN2 + gate + routing + gather
    resgate_k<<<T1024, 256>>>(x, p_tmp, aob, ln2w, ln2b, gatew, gateb, p_xres);

    // join: MoE GEMMs need converted weights
    cudaStreamWaitEvent(0, evJoin, 0);

    // fc GEMM: 64x64 tiles for wave-fill (320 -> ~1280 live CTAs)
    gemm_async<64,64,32,32,32><<<dim3(FC_N/64, T1024/64, E), 128>>>(
        pb_xg, D, (long)T1024 * D, pb_fcw, FC_N, (long)D * FC_N,
        p_h12, FC_N, (long)T1024 * FC_N, D, p_cnt);

    moe_act_k<<<dim3(F/256, 256, E), 256>>>(fcb);

    // expert-out GEMM: 64x64 tiles for occupancy
    gemm_async<64,64,32,32,32><<<dim3(D/64, T1024/64, E), 128>>>(
        pb_act, F, (long)T1024 * F, pb_eow, D, (long)F * D,
        p_y, D, (long)T1024 * D, F, p_cnt);

    scatter_k<<<dim3(E, 256), 256>>>(eob, out);

    if (out_size > T1024 * D)
        moe_loss_k<<<1, 32>>>(out + (long)T1024 * D);
}

// round 17
// speedup vs baseline: 1.6615x; 1.6615x over previous
#include <cuda_runtime.h>
#include <cuda_bf16.h>
#include <mma.h>
#include <math.h>
#include <cstdint>
using namespace nvcuda;

// ---------------- constants ----------------
#define T1024 1024
#define D 1024
#define H 16
#define HD 64
#define E 8
#define F 2560
#define QKVN 3072
#define FC_N (2*F)   // 5120

typedef __nv_bfloat16 bf16;

// ---------------- scratch (device globals) ----------------
__device__ float g_qkv[T1024 * QKVN];
__device__ float g_tmp[T1024 * D];
__device__ float g_xres[T1024 * D];
__device__ float g_h12[(long)E * T1024 * FC_N];
__device__ float g_y[(long)E * T1024 * D];
__device__ int   g_cnt[E];
__device__ float g_sums[E];
__device__ int   g_tok[E * T1024];
__device__ float g_gwf[T1024];
__device__ float g_cs[T1024 * 32];
__device__ float g_sn[T1024 * 32];

__device__ bf16 b_h1[T1024 * D];
__device__ bf16 b_qkv[T1024 * QKVN];
__device__ bf16 b_attn[T1024 * D];
__device__ bf16 b_xg[E * T1024 * D];
__device__ bf16 b_act[(long)E * T1024 * F];
__device__ bf16 b_qkvw[D * QKVN];
__device__ bf16 b_aow[D * D];
__device__ bf16 b_fcw[(long)E * D * FC_N];
__device__ bf16 b_eow[(long)E * F * D];

// ---------------- cp.async helpers ----------------
__device__ __forceinline__ void cp16(unsigned int s, const void* g) {
    asm volatile("cp.async.cg.shared.global [%0], [%1], 16;\n" :: "r"(s), "l"(g));
}
__device__ __forceinline__ void cp_commit() {
    asm volatile("cp.async.commit_group;\n");
}
template<int N> __device__ __forceinline__ void cp_wait() {
    asm volatile("cp.async.wait_group %0;\n" :: "n"(N));
}

// ---------------- small kernels ----------------
// fused: zero counters + rope tables
__global__ void init_k() {
    int t = blockIdx.x, j = threadIdx.x;   // 32 threads
    if (t == 0 && j < E) { g_cnt[j] = 0; g_sums[j] = 0.f; }
    float inv = powf(10000.f, -(2.f * (float)j) / 64.f);
    float fr = (float)t * inv;
    g_cs[t * 32 + j] = cosf(fr);
    g_sn[t * 32 + j] = sinf(fr);
}

// fp32 -> bf16 convert, 8 elems/thread
__global__ void f2b_k(const float* __restrict__ src, bf16* __restrict__ dst, long n) {
    long i = ((long)blockIdx.x * 256 + threadIdx.x) * 8;
    if (i >= n) return;
    float4 a = *(const float4*)&src[i];
    float4 b = *(const float4*)&src[i + 4];
    __nv_bfloat162 r[4];
    r[0] = __floats2bfloat162_rn(a.x, a.y);
    r[1] = __floats2bfloat162_rn(a.z, a.w);
    r[2] = __floats2bfloat162_rn(b.x, b.y);
    r[3] = __floats2bfloat162_rn(b.z, b.w);
    *(uint4*)&dst[i] = *(uint4*)r;
}

__global__ void layernorm_k(const float* __restrict__ x, const float* __restrict__ w,
                            const float* __restrict__ b, bf16* __restrict__ y) {
    int t = blockIdx.x, tid = threadIdx.x;
    const float* xr = x + (long)t * D;
    float v[4], s = 0.f, ss = 0.f;
#pragma unroll
    for (int i = 0; i < 4; i++) {
        float a = xr[tid + i * 256];
        v[i] = a; s += a; ss += a * a;
    }
    __shared__ float r1[256], r2[256];
    r1[tid] = s; r2[tid] = ss; __syncthreads();
    for (int st = 128; st > 0; st >>= 1) {
        if (tid < st) { r1[tid] += r1[tid + st]; r2[tid] += r2[tid + st]; }
        __syncthreads();
    }
    float mean = r1[0] * (1.f / D);
    float var  = r2[0] * (1.f / D) - mean * mean;
    float inv  = rsqrtf(var + 1e-5f);
#pragma unroll
    for (int i = 0; i < 4; i++) {
        int d = tid + i * 256;
        y[(long)t * D + d] = __float2bfloat16((v[i] - mean) * inv * w[d] + b[d]);
    }
}

// fused: xres = x+tmp+bias ; h2 = LN(xres) ; gate softmax/argmax + routing + bf16 gather
__global__ void resgate_k(const float* __restrict__ x, const float* __restrict__ tmp,
                          const float* __restrict__ bias,
                          const float* __restrict__ w, const float* __restrict__ b,
                          const float* __restrict__ gw_mat, const float* __restrict__ gb,
                          float* __restrict__ xres) {
    int t = blockIdx.x, tid = threadIdx.x;
    int wrp = tid >> 5, lane = tid & 31;
    float v[4], s = 0.f, ss = 0.f;
#pragma unroll
    for (int i = 0; i < 4; i++) {
        int d = tid + i * 256;
        float a = x[(long)t * D + d] + tmp[(long)t * D + d] + bias[d];
        v[i] = a; s += a; ss += a * a;
        xres[(long)t * D + d] = a;
    }
    __shared__ float r1[256], r2[256];
    r1[tid] = s; r2[tid] = ss; __syncthreads();
    for (int st = 128; st > 0; st >>= 1) {
        if (tid < st) { r1[tid] += r1[tid + st]; r2[tid] += r2[tid + st]; }
        __syncthreads();
    }
    float mean = r1[0] * (1.f / D);
    float var  = r2[0] * (1.f / D) - mean * mean;
    float inv  = rsqrtf(var + 1e-5f);
    float h2v[4];
    float p[E];
#pragma unroll
    for (int e = 0; e < E; e++) p[e] = 0.f;
#pragma unroll
    for (int i = 0; i < 4; i++) {
        int d = tid + i * 256;
        float hv = (v[i] - mean) * inv * w[d] + b[d];
        h2v[i] = hv;
#pragma unroll
        for (int e = 0; e < E; e++) p[e] += hv * gw_mat[d * E + e];
    }
    __shared__ float wsum[8][E];
#pragma unroll
    for (int e = 0; e < E; e++) {
        float pv = p[e];
#pragma unroll
        for (int o = 16; o > 0; o >>= 1)
            pv += __shfl_xor_sync(0xffffffffu, pv, o);
        if (lane == 0) wsum[wrp][e] = pv;
    }
    __syncthreads();
    __shared__ int sh_slot, sh_e;
    if (tid == 0) {
        float logits[E];
        for (int e = 0; e < E; e++) {
            float acc = 0.f;
            for (int q = 0; q < 8; q++) acc += wsum[q][e];
            logits[e] = acc + gb[e];
        }
        float mx = -3.4e38f;
        for (int e = 0; e < E; e++) mx = fmaxf(mx, logits[e]);
        float Z = 0.f, pr[E];
        for (int e = 0; e < E; e++) { pr[e] = expf(logits[e] - mx); Z += pr[e]; }
        float best = -1.f; int bi = 0;
        for (int e = 0; e < E; e++) {
            float pv = pr[e] / Z;
            if (pv > best) { best = pv; bi = e; }
        }
        int slot = atomicAdd(&g_cnt[bi], 1);
        atomicAdd(&g_sums[bi], best);
        g_tok[bi * T1024 + slot] = t;
        g_gwf[t] = best;
        sh_slot = slot; sh_e = bi;
    }
    __syncthreads();
    bf16* dst = b_xg + ((long)sh_e * T1024 + sh_slot) * D;
#pragma unroll
    for (int i = 0; i < 4; i++)
        dst[tid + i * 256] = __float2bfloat16(h2v[i]);
}

// fused qkv bias + rope (table); writes bf16 qkv
__global__ void qkvpost_k(const float* __restrict__ b) {
    int t = blockIdx.x;
    const float* row = g_qkv + (long)t * QKVN;
    bf16* orow = b_qkv + (long)t * QKVN;
    for (int c = threadIdx.x; c < QKVN; c += blockDim.x) {
        float val;
        if (c < 2 * D) {
            int part = c / D;          // 0=q, 1=k
            int within = c - part * D;
            int d = within & 63;
            int j = d & 31;
            float cs = g_cs[t * 32 + j], sn = g_sn[t * 32 + j];
            int h = within >> 6;
            int base = part * D + h * HD;
            float x1 = row[base + j]      + b[base + j];
            float x2 = row[base + j + 32] + b[base + j + 32];
            val = (d < 32) ? (x1 * cs - x2 * sn) : (x1 * sn + x2 * cs);
        } else {
            val = row[c] + b[c];
        }
        orow[c] = __float2bfloat16(val);
    }
}

// ---------------- fused flash attention (double-buffered K/V) ----------------
#define FA_QP 72
#define FA_SP 132
#define FA_PP 136
#define FA_OP 68
#define OFF_Q 0
#define KV_STG (2 * 128 * FA_QP * 2)
#define OFF_KV0 (128 * FA_QP * 2)
#define OFF_S (OFF_KV0 + 2 * KV_STG)
#define OFF_P (OFF_S + 8 * 16 * FA_SP * 4)
#define OFF_O (OFF_P + 8 * 16 * FA_PP * 2)
#define OFF_M (OFF_O + 8 * 16 * FA_OP * 4)
#define OFF_L (OFF_M + 128 * 4)
#define OFF_G (OFF_L + 128 * 4)
#define FA_SMEM (OFF_G + 132 * 4)

__global__ void __launch_bounds__(256) fa_k(const int* __restrict__ ids) {
    extern __shared__ char sm[];
    bf16*  Qs = (bf16*)(sm + OFF_Q);
    float* Sb = (float*)(sm + OFF_S);
    bf16*  Pb = (bf16*)(sm + OFF_P);
    float* Ob = (float*)(sm + OFF_O);
    float* Mr = (float*)(sm + OFF_M);
    float* Lr = (float*)(sm + OFF_L);
    int*   Gf = (int*)(sm + OFF_G);
    unsigned sbase = (unsigned)__cvta_generic_to_shared(sm);

    int qt = blockIdx.x, h = blockIdx.y;
    int qbase = qt * 128;
    int tid = threadIdx.x, w = tid >> 5, lane = tid & 31;

    for (int i = tid; i < 128 * 8; i += 256) {
        int r = i >> 3, c8 = (i & 7) * 8;
        cp16(sbase + OFF_Q + (r * FA_QP + c8) * 2,
             &b_qkv[(long)(qbase + r) * QKVN + h * HD + c8]);
    }
    cp_commit();

    auto issueKV = [&](int stage, int kt) {
        unsigned kb = sbase + OFF_KV0 + stage * KV_STG;
        unsigned vb = kb + 128 * FA_QP * 2;
        for (int i = tid; i < 128 * 8; i += 256) {
            int r = i >> 3, c8 = (i & 7) * 8;
            long goff = (long)(kt * 128 + r) * QKVN + h * HD + c8;
            cp16(kb + (r * FA_QP + c8) * 2, &b_qkv[goff + D]);
            cp16(vb + (r * FA_QP + c8) * 2, &b_qkv[goff + 2 * D]);
        }
    };

    issueKV(0, 0);
    cp_commit();

    if (tid < 128) {
        int id = ids[qbase + tid];
        Gf[tid] = (id >= 2 && id < 8) ? 1 : 0;
        Mr[tid] = -3.0e38f;
        Lr[tid] = 0.f;
    }
    for (int i = tid; i < 8 * 16 * FA_OP; i += 256) Ob[i] = 0.f;
    cp_wait<1>();
    __syncthreads();
    if (tid == 0) {
        int any = 0;
        for (int i = 0; i < 128; i++) any |= Gf[i];
        Gf[128] = any ? 8 : (qt + 1);
    }
    __syncthreads();
    int ntiles = Gf[128];

    wmma::fragment<wmma::matrix_a, 16, 16, 16, bf16, wmma::row_major> qa[4];
#pragma unroll
    for (int k16 = 0; k16 < 4; k16++)
        wmma::load_matrix_sync(qa[k16], &Qs[(w * 16) * FA_QP + k16 * 16], FA_QP);

    float* Sw = Sb + w * 16 * FA_SP;
    bf16*  Pw = Pb + w * 16 * FA_PP;
    float* Ow = Ob + w * 16 * FA_OP;

    for (int kt = 0; kt < ntiles; kt++) {
        if (kt + 1 < ntiles) issueKV((kt + 1) & 1, kt + 1);
        cp_commit();
        cp_wait<1>();
        __syncthreads();

        bf16* Ks = (bf16*)(sm + OFF_KV0 + (kt & 1) * KV_STG);
        bf16* Vs = Ks + 128 * FA_QP;

        wmma::fragment<wmma::accumulator, 16, 16, 16, float> sacc[8];
#pragma unroll
        for (int j = 0; j < 8; j++) wmma::fill_fragment(sacc[j], 0.f);
#pragma unroll
        for (int k16 = 0; k16 < 4; k16++) {
#pragma unroll
            for (int j = 0; j < 8; j++) {
                wmma::fragment<wmma::matrix_b, 16, 16, 16, bf16, wmma::col_major> kb;
                wmma::load_matrix_sync(kb, &Ks[(j * 16) * FA_QP + k16 * 16], FA_QP);
                wmma::mma_sync(sacc[j], qa[k16], kb, sacc[j]);
            }
        }
#pragma unroll
        for (int j = 0; j < 8; j++)
            wmma::store_matrix_sync(&Sw[j * 16], sacc[j], FA_SP, wmma::mem_row_major);
        __syncwarp();

#pragma unroll 1
        for (int r = 0; r < 16; r++) {
            int rg = w * 16 + r;
            int q = qbase + rg;
            bool gl = Gf[rg] != 0;
            float v[4];
#pragma unroll
            for (int u = 0; u < 4; u++) {
                int c = lane + u * 32;
                int k = kt * 128 + c;
                float s = Sw[r * FA_SP + c];
                v[u] = (gl || k <= q) ? s * 0.125f : -3.4e38f;
            }
            float mx = fmaxf(fmaxf(v[0], v[1]), fmaxf(v[2], v[3]));
#pragma unroll
            for (int o = 16; o > 0; o >>= 1)
                mx = fmaxf(mx, __shfl_xor_sync(0xffffffffu, mx, o));
            float mo = Mr[rg];
            float mn = fmaxf(mo, mx);
            float al = __expf(mo - mn);
            float sum = 0.f;
#pragma unroll
            for (int u = 0; u < 4; u++) {
                float p = __expf(v[u] - mn);
                sum += p;
                Pw[r * FA_PP + lane + u * 32] = __float2bfloat16(p);
            }
#pragma unroll
            for (int o = 16; o > 0; o >>= 1)
                sum += __shfl_xor_sync(0xffffffffu, sum, o);
            Ow[r * FA_OP + lane]      *= al;
            Ow[r * FA_OP + lane + 32] *= al;
            if (lane == 0) {
                Mr[rg] = mn;
                Lr[rg] = Lr[rg] * al + sum;
            }
        }
        __syncwarp();

        wmma::fragment<wmma::accumulator, 16, 16, 16, float> oacc[4];
#pragma unroll
        for (int j = 0; j < 4; j++)
            wmma::load_matrix_sync(oacc[j], &Ow[j * 16], FA_OP, wmma::mem_row_major);
#pragma unroll
        for (int k16 = 0; k16 < 8; k16++) {
            wmma::fragment<wmma::matrix_a, 16, 16, 16, bf16, wmma::row_major> pa;
            wmma::load_matrix_sync(pa, &Pw[k16 * 16], FA_PP);
#pragma unroll
            for (int j = 0; j < 4; j++) {
                wmma::fragment<wmma::matrix_b, 16, 16, 16, bf16, wmma::row_major> vb;
                wmma::load_matrix_sync(vb, &Vs[(k16 * 16) * FA_QP + j * 16], FA_QP);
                wmma::mma_sync(oacc[j], pa, vb, oacc[j]);
            }
        }
#pragma unroll
        for (int j = 0; j < 4; j++)
            wmma::store_matrix_sync(&Ow[j * 16], oacc[j], FA_OP, wmma::mem_row_major);
        __syncthreads();
    }

#pragma unroll 1
    for (int r = 0; r < 16; r++) {
        int rg = w * 16 + r;
        float inv = 1.f / Lr[rg];
        int t = qbase + rg;
        b_attn[(long)t * D + h * HD + lane]      = __float2bfloat16(Ow[r * FA_OP + lane] * inv);
        b_attn[(long)t * D + h * HD + lane + 32] = __float2bfloat16(Ow[r * FA_OP + lane + 32] * inv);
    }
}

// ---------------- all-bf16 cp.async 3-stage pipelined tensor GEMM ----------------
template<int BM, int BN, int BK, int WM, int WN>
__global__ void __launch_bounds__((BM / WM) * (BN / WN) * 32, 2)
gemm_async(const bf16* __restrict__ A, int lda, long sA,
           const bf16* __restrict__ B, int ldb, long sB,
           float* __restrict__ C, int ldc, long sC,
           int K, const int* __restrict__ cntPtr) {
    int z = blockIdx.z;
    int m0 = blockIdx.y * BM;
    if (cntPtr && m0 >= cntPtr[z]) return;
    int n0 = blockIdx.x * BN;
    A += (long)z * sA; B += (long)z * sB; C += (long)z * sC;

    constexpr int S = 3;
    constexpr int AP = BK + 8;
    constexpr int BP = BN + 8;
    __shared__ __align__(16) bf16 As[S][BM][AP];
    __shared__ __align__(16) bf16 Bs[S][BK][BP];

    constexpr int WARPS_M = BM / WM;
    constexpr int WARPS_N = BN / WN;
    constexpr int NT = WARPS_M * WARPS_N * 32;
    constexpr int MI = WM / 16, NI = WN / 16;
    constexpr int ACH = BM * BK / 8;
    constexpr int BCH = BK * BN / 8;

    int tid = threadIdx.x;
    int w = tid >> 5;
    int wm = w % WARPS_M, wn = w / WARPS_M;
    int mw0 = wm * WM, nw0 = wn * WN;

    int nIter = K / BK;

    unsigned int sA0 = (unsigned int)__cvta_generic_to_shared(&As[0][0][0]);
    unsigned int sB0 = (unsigned int)__cvta_generic_to_shared(&Bs[0][0][0]);
    constexpr unsigned int A_STG = BM * AP * 2;
    constexpr unsigned int B_STG = BK * BP * 2;

    auto issue = [&](int stage, int k0) {
#pragma unroll
        for (int c = tid; c < ACH; c += NT) {
            int row = c / (BK / 8);
            int col = (c % (BK / 8)) * 8;
            cp16(sA0 + stage * A_STG + (row * AP + col) * 2,
                 &A[(long)(m0 + row) * lda + k0 + col]);
        }
#pragma unroll
        for (int c = tid; c < BCH; c += NT) {
            int kk = c / (BN / 8);
            int col = (c % (BN / 8)) * 8;
            cp16(sB0 + stage * B_STG + (kk * BP + col) * 2,
                 &B[(long)(k0 + kk) * ldb + n0 + col]);
        }
    };

#pragma unroll
    for (int s = 0; s < S - 1; s++) {
        if (s < nIter) issue(s, s * BK);
        cp_commit();
    }

    wmma::fragment<wmma::accumulator, 16, 16, 16, float> acc[MI][NI];
#pragma unroll
    for (int i = 0; i < MI; i++)
#pragma unroll
        for (int j = 0; j < NI; j++) wmma::fill_fragment(acc[i][j], 0.f);

    for (int it = 0; it < nIter; it++) {
        cp_wait<S - 2>();
        __syncthreads();
        int st = it % S;
#pragma unroll
        for (int k16 = 0; k16 < BK; k16 += 16) {
            wmma::fragment<wmma::matrix_b, 16, 16, 16, bf16, wmma::row_major> bfr[NI];
#pragma unroll
            for (int j = 0; j < NI; j++)
                wmma::load_matrix_sync(bfr[j], &Bs[st][k16][nw0 + j * 16], BP);
#pragma unroll
            for (int i = 0; i < MI; i++) {
                wmma::fragment<wmma::matrix_a, 16, 16, 16, bf16, wmma::row_major> af;
                wmma::load_matrix_sync(af, &As[st][mw0 + i * 16][k16], AP);
#pragma unroll
                for (int j = 0; j < NI; j++)
                    wmma::mma_sync(acc[i][j], af, bfr[j], acc[i][j]);
            }
        }
        int pf = it + S - 1;
        if (pf < nIter) issue(pf % S, pf * BK);
        cp_commit();
    }
#pragma unroll
    for (int i = 0; i < MI; i++)
#pragma unroll
        for (int j = 0; j < NI; j++)
            wmma::store_matrix_sync(&C[(long)(m0 + mw0 + i * 16) * ldc + n0 + nw0 + j * 16],
                                    acc[i][j], ldc, wmma::mem_row_major);
}

// GLU activation with fused fc bias (exact gelu) -> bf16; m-strided grid
__global__ void moe_act_k(const float* __restrict__ fcb) {
    int e = blockIdx.z;
    int cp = (g_cnt[e] + 127) & ~127;
    int f = blockIdx.x * 256 + threadIdx.x;
    const float* b = fcb + (long)e * FC_N;
    float b1 = b[f], b2 = b[F + f];
    for (int m = blockIdx.y; m < cp; m += gridDim.y) {
        const float* row = g_h12 + ((long)e * T1024 + m) * FC_N;
        float x1 = row[f] + b1;
        float x2 = row[F + f] + b2;
        float g = 0.5f * x2 * (1.f + erff(x2 * 0.70710678118654752f));
        b_act[((long)e * T1024 + m) * F + f] = __float2bfloat16(x1 * g);
    }
}

// scatter epilogue: out[t] = xres[t] + (y[m] + eout_b) * gw[t]; m-strided grid
__global__ void scatter_k(const float* __restrict__ eob, float* __restrict__ out) {
    int e = blockIdx.x;
    int cnt = g_cnt[e];
    const float* bias = eob + (long)e * D;
    for (int m = blockIdx.y; m < cnt; m += gridDim.y) {
        int t = g_tok[e * T1024 + m];
        float g = g_gwf[t];
        const float* y = g_y + ((long)e * T1024 + m) * D;
        for (int d = threadIdx.x; d < D; d += 256)
            out[(long)t * D + d] = g_xres[(long)t * D + d] + (y[d] + bias[d]) * g;
    }
}

__global__ void moe_loss_k(float* __restrict__ out_loss) {
    if (threadIdx.x == 0) {
        float l = 0.f;
        for (int e = 0; e < E; e++) {
            float u = g_sums[e] / ((float)g_cnt[e] + 1e-8f);
            float d = u - 1.f / (float)E;
            l += d * d;
        }
        out_loss[0] = l;
    }
}

// ---------------- host ----------------
static void* sym_addr(const void* sym) {
    void* p = nullptr;
    cudaGetSymbolAddress(&p, sym);
    return p;
}

extern "C" void kernel_launch(void* const* d_in, const int* in_sizes, int n_in,
                              void* d_out, int out_size) {
    const float* x      = (const float*)d_in[0];
    const int*   ids    = (const int*)d_in[1];
    const float* ln1w   = (const float*)d_in[2];
    const float* ln1b   = (const float*)d_in[3];
    const float* qkvw   = (const float*)d_in[4];
    const float* qkvb   = (const float*)d_in[5];
    const float* aow    = (const float*)d_in[6];
    const float* aob    = (const float*)d_in[7];
    const float* ln2w   = (const float*)d_in[8];
    const float* ln2b   = (const float*)d_in[9];
    const float* gatew  = (const float*)d_in[10];
    const float* gateb  = (const float*)d_in[11];
    const float* fcw    = (const float*)d_in[12];
    const float* fcb    = (const float*)d_in[13];
    const float* eow    = (const float*)d_in[14];
    const float* eob    = (const float*)d_in[15];
    float* out = (float*)d_out;

    float* p_qkv  = (float*)sym_addr(g_qkv);
    float* p_tmp  = (float*)sym_addr(g_tmp);
    float* p_xres = (float*)sym_addr(g_xres);
    float* p_h12  = (float*)sym_addr(g_h12);
    float* p_y    = (float*)sym_addr(g_y);
    int*   p_cnt  = (int*)sym_addr(g_cnt);
    bf16* pb_h1   = (bf16*)sym_addr(b_h1);
    bf16* pb_qkv  = (bf16*)sym_addr(b_qkv);
    bf16* pb_attn = (bf16*)sym_addr(b_attn);
    bf16* pb_xg   = (bf16*)sym_addr(b_xg);
    bf16* pb_act  = (bf16*)sym_addr(b_act);
    bf16* pb_qkvw = (bf16*)sym_addr(b_qkvw);
    bf16* pb_aow  = (bf16*)sym_addr(b_aow);
    bf16* pb_fcw  = (bf16*)sym_addr(b_fcw);
    bf16* pb_eow  = (bf16*)sym_addr(b_eow);

    static cudaStream_t s2 = nullptr;
    static cudaEvent_t evFork = nullptr, evJoin = nullptr;
    if (!s2) {
        cudaStreamCreateWithFlags(&s2, cudaStreamNonBlocking);
        cudaEventCreateWithFlags(&evFork, cudaEventDisableTiming);
        cudaEventCreateWithFlags(&evJoin, cudaEventDisableTiming);
        cudaFuncSetAttribute(fa_k, cudaFuncAttributeMaxDynamicSharedMemorySize, FA_SMEM);
    }

    // fork side stream: MoE weight + aow converts overlap the attention chain
    cudaEventRecord(evFork, 0);
    cudaStreamWaitEvent(s2, evFork, 0);
    f2b_k<<<(D * D) / (8 * 256), 256, 0, s2>>>(aow, pb_aow, (long)D * D);
    f2b_k<<<(int)(((long)E * D * FC_N) / (8 * 256)), 256, 0, s2>>>(fcw, pb_fcw, (long)E * D * FC_N);
    f2b_k<<<(int)(((long)E * F * D) / (8 * 256)), 256, 0, s2>>>(eow, pb_eow, (long)E * F * D);
    cudaEventRecord(evJoin, s2);

    // main stream: attention chain
    init_k<<<T1024, 32>>>();
    f2b_k<<<(D * QKVN) / (8 * 256), 256>>>(qkvw, pb_qkvw, (long)D * QKVN);

    layernorm_k<<<T1024, 256>>>(x, ln1w, ln1b, pb_h1);

    // QKV GEMM: 128x128 (large-N GEMM; 64x64 thrashes L2 — R16 lesson)
    gemm_async<128,128,32,64,64><<<dim3(QKVN/128, T1024/128, 1), 128>>>(
        pb_h1, D, 0, pb_qkvw, QKVN, 0, p_qkv, QKVN, 0, D, nullptr);

    qkvpost_k<<<T1024, 768>>>(qkvb);

    fa_k<<<dim3(T1024/128, H), 256, FA_SMEM>>>(ids);

    // Wo GEMM: 64x64 tiles for occupancy (small GEMM — proven win)
    gemm_async<64,64,32,32,32><<<dim3(D/64, T1024/64, 1), 128>>>(
        pb_attn, D, 0, pb_aow, D, 0, p_tmp, D, 0, D, nullptr);

    // fused residual + LN2 + gate + routing + gather
    resgate_k<<<T1024, 256>>>(x, p_tmp, aob, ln2w, ln2b, gatew, gateb, p_xres);

    // join: MoE GEMMs need converted weights
    cudaStreamWaitEvent(0, evJoin, 0);

    // fc GEMM: 128x128 (large-N GEMM)
    gemm_async<128,128,32,64,64><<<dim3(FC_N/128, T1024/128, E), 128>>>(
        pb_xg, D, (long)T1024 * D, pb_fcw, FC_N, (long)D * FC_N,
        p_h12, FC_N, (long)T1024 * FC_N, D, p_cnt);

    moe_act_k<<<dim3(F/256, 256, E), 256>>>(fcb);

    // expert-out GEMM: 64x64 tiles for occupancy (small GEMM — proven win)
    gemm_async<64,64,32,32,32><<<dim3(D/64, T1024/64, E), 128>>>(
        pb_act, F, (long)T1024 * F, pb_eow, D, (long)F * D,
        p_y, D, (long)T1024 * D, F, p_cnt);

    scatter_k<<<dim3(E, 256), 256>>>(eob, out);

    if (out_size > T1024 * D)
        moe_loss_k<<<1, 32>>>(out + (long)T1024 * D);
}